// round 3
// baseline (speedup 1.0000x reference)
#include <cuda_runtime.h>

#define NEXP 5
#define HID  20
#define TPT  8   // tokens per thread (4 f32x2 pairs)

typedef unsigned long long ull;

__device__ __forceinline__ ull pack2(float lo, float hi) {
    ull r;
    asm("mov.b64 %0, {%1, %2};" : "=l"(r) : "f"(lo), "f"(hi));
    return r;
}
__device__ __forceinline__ void unpack2(ull v, float& lo, float& hi) {
    asm("mov.b64 {%0, %1}, %2;" : "=f"(lo), "=f"(hi) : "l"(v));
}
__device__ __forceinline__ ull fma2(ull a, ull b, ull c) {
    ull r;
    asm("fma.rn.f32x2 %0, %1, %2, %3;" : "=l"(r) : "l"(a), "l"(b), "l"(c));
    return r;
}
__device__ __forceinline__ ull relu2(ull v) {
    float lo, hi;
    unpack2(v, lo, hi);
    return pack2(fmaxf(lo, 0.0f), fmaxf(hi, 0.0f));
}

__global__ __launch_bounds__(128) void moe_kernel(
    const float* __restrict__ x,
    const float* __restrict__ W1, const float* __restrict__ b1,
    const float* __restrict__ W2, const float* __restrict__ b2,
    const float* __restrict__ Wg, const float* __restrict__ bg,
    float* __restrict__ out_mixed, float* __restrict__ out_gate,
    int ngroups)
{
    // Tight-packed weights: 2x LDS.128 per (e,h); f32x2 broadcasts built in
    // registers once per (e,h) and reused across 4 token-pairs.
    __shared__ float4 s_w1[NEXP * HID];  // {W1[e,0,h], W1[e,1,h], W1[e,2,h], b1[e,h]}
    __shared__ float4 s_w2[NEXP * HID];  // {W2[e,h,0], W2[e,h,1], W2[e,h,2], 0}
    __shared__ float4 s_b2[NEXP];        // {b2[e,0..2], 0}
    __shared__ float4 s_gw[NEXP];        // {Wg[0,e], Wg[1,e], Wg[2,e], bg[e]}

    int t = threadIdx.x;
    if (t < NEXP * HID) {
        int e = t / HID, h = t % HID;
        s_w1[t] = make_float4(W1[(e * 3 + 0) * HID + h],
                              W1[(e * 3 + 1) * HID + h],
                              W1[(e * 3 + 2) * HID + h],
                              b1[e * HID + h]);
        s_w2[t] = make_float4(W2[(e * HID + h) * 3 + 0],
                              W2[(e * HID + h) * 3 + 1],
                              W2[(e * HID + h) * 3 + 2],
                              0.0f);
    } else if (t < NEXP * HID + NEXP) {
        int e = t - NEXP * HID;
        s_gw[e] = make_float4(Wg[0 * NEXP + e], Wg[1 * NEXP + e], Wg[2 * NEXP + e], bg[e]);
        s_b2[e] = make_float4(b2[e * 3 + 0], b2[e * 3 + 1], b2[e * 3 + 2], 0.0f);
    }
    __syncthreads();

    int gid = blockIdx.x * blockDim.x + threadIdx.x;  // group of 8 tokens
    if (gid >= ngroups) return;

    // ---- Load 8 tokens' x (24 floats = 6x LDG.128, contiguous per thread) ----
    const float4* x4 = (const float4*)x;
    float v[24];
    #pragma unroll
    for (int i = 0; i < 6; i++) {
        float4 f = x4[6 * gid + i];
        v[4 * i + 0] = f.x; v[4 * i + 1] = f.y; v[4 * i + 2] = f.z; v[4 * i + 3] = f.w;
    }
    // token-pair p = tokens (2p, 2p+1); component c of token j is v[3j+c]
    ull x0p[4], x1p[4], x2p[4];
    #pragma unroll
    for (int p = 0; p < 4; p++) {
        x0p[p] = pack2(v[6 * p + 0], v[6 * p + 3]);
        x1p[p] = pack2(v[6 * p + 1], v[6 * p + 4]);
        x2p[p] = pack2(v[6 * p + 2], v[6 * p + 5]);
    }

    // ---- Gate: logits + softmax (scalar, 8 tokens) ----
    float g[TPT][NEXP];
    #pragma unroll
    for (int e = 0; e < NEXP; e++) {
        float4 w = s_gw[e];
        #pragma unroll
        for (int j = 0; j < TPT; j++)
            g[j][e] = fmaf(v[3 * j + 0], w.x,
                      fmaf(v[3 * j + 1], w.y,
                      fmaf(v[3 * j + 2], w.z, w.w)));
    }
    #pragma unroll
    for (int j = 0; j < TPT; j++) {
        float m = g[j][0];
        #pragma unroll
        for (int e = 1; e < NEXP; e++) m = fmaxf(m, g[j][e]);
        float s = 0.0f;
        #pragma unroll
        for (int e = 0; e < NEXP; e++) { g[j][e] = __expf(g[j][e] - m); s += g[j][e]; }
        float inv = __fdividef(1.0f, s);
        #pragma unroll
        for (int e = 0; e < NEXP; e++) g[j][e] *= inv;
    }

    // Store gate output early (40 floats = 10x STG.128).
    {
        float4* og = (float4*)out_gate;
        float ga[TPT * NEXP];
        #pragma unroll
        for (int j = 0; j < TPT; j++)
            #pragma unroll
            for (int e = 0; e < NEXP; e++) ga[5 * j + e] = g[j][e];
        #pragma unroll
        for (int i = 0; i < 10; i++)
            og[10 * gid + i] = make_float4(ga[4*i], ga[4*i+1], ga[4*i+2], ga[4*i+3]);
    }

    // ---- Experts: fc1 + ReLU + fc2 (packed), gate-mixed ----
    ull zero = pack2(0.0f, 0.0f);
    ull mix0[4] = {zero, zero, zero, zero};
    ull mix1[4] = {zero, zero, zero, zero};
    ull mix2[4] = {zero, zero, zero, zero};

    #pragma unroll
    for (int e = 0; e < NEXP; e++) {
        // acc init = b2 (bias folded into accumulator)
        float4 bb = s_b2[e];
        ull bb0 = pack2(bb.x, bb.x), bb1 = pack2(bb.y, bb.y), bb2 = pack2(bb.z, bb.z);
        ull acc0[4], acc1[4], acc2[4];
        #pragma unroll
        for (int p = 0; p < 4; p++) { acc0[p] = bb0; acc1[p] = bb1; acc2[p] = bb2; }

        #pragma unroll
        for (int h = 0; h < HID; h++) {
            float4 w1 = s_w1[e * HID + h];
            float4 w2 = s_w2[e * HID + h];
            ull w1x = pack2(w1.x, w1.x), w1y = pack2(w1.y, w1.y);
            ull w1z = pack2(w1.z, w1.z), b1d = pack2(w1.w, w1.w);
            ull w2x = pack2(w2.x, w2.x), w2y = pack2(w2.y, w2.y);
            ull w2z = pack2(w2.z, w2.z);
            #pragma unroll
            for (int p = 0; p < 4; p++) {
                ull hv = fma2(x0p[p], w1x, fma2(x1p[p], w1y, fma2(x2p[p], w1z, b1d)));
                hv = relu2(hv);
                acc0[p] = fma2(hv, w2x, acc0[p]);
                acc1[p] = fma2(hv, w2y, acc1[p]);
                acc2[p] = fma2(hv, w2z, acc2[p]);
            }
        }
        #pragma unroll
        for (int p = 0; p < 4; p++) {
            ull gp = pack2(g[2 * p][e], g[2 * p + 1][e]);
            mix0[p] = fma2(gp, acc0[p], mix0[p]);
            mix1[p] = fma2(gp, acc1[p], mix1[p]);
            mix2[p] = fma2(gp, acc2[p], mix2[p]);
        }
    }

    // ---- Unpack and store mixed (24 floats = 6x STG.128) ----
    float ma[24];
    #pragma unroll
    for (int p = 0; p < 4; p++) {
        float lo, hi;
        unpack2(mix0[p], lo, hi); ma[6 * p + 0] = lo; ma[6 * p + 3] = hi;
        unpack2(mix1[p], lo, hi); ma[6 * p + 1] = lo; ma[6 * p + 4] = hi;
        unpack2(mix2[p], lo, hi); ma[6 * p + 2] = lo; ma[6 * p + 5] = hi;
    }
    float4* om = (float4*)out_mixed;
    #pragma unroll
    for (int i = 0; i < 6; i++)
        om[6 * gid + i] = make_float4(ma[4*i], ma[4*i+1], ma[4*i+2], ma[4*i+3]);
}

extern "C" void kernel_launch(void* const* d_in, const int* in_sizes, int n_in,
                              void* d_out, int out_size)
{
    // Input order per setup_inputs: x, W1, b1, W2, b2, Wg, bg
    const float* x  = (const float*)d_in[0];
    const float* W1 = (const float*)d_in[1];
    const float* b1 = (const float*)d_in[2];
    const float* W2 = (const float*)d_in[3];
    const float* b2 = (const float*)d_in[4];
    const float* Wg = (const float*)d_in[5];
    const float* bg = (const float*)d_in[6];

    int B = in_sizes[0] / 3;           // x is [B, 3]
    int ngroups = B / TPT;             // 8 tokens per thread

    float* out_mixed = (float*)d_out;            // [B, 3]
    float* out_gate  = (float*)d_out + 3 * B;    // [B, 5]

    int threads = 128;
    int blocks = (ngroups + threads - 1) / threads;
    moe_kernel<<<blocks, threads>>>(x, W1, b1, W2, b2, Wg, bg,
                                    out_mixed, out_gate, ngroups);
}

// round 4
// speedup vs baseline: 1.4316x; 1.4316x over previous
#include <cuda_runtime.h>

#define NEXP 5
#define HID  20
#define NP   10   // hidden-unit pairs per expert
#define TPT  4    // tokens per thread

typedef unsigned long long ull;

__device__ __forceinline__ ull pack2(float lo, float hi) {
    ull r;
    asm("mov.b64 %0, {%1, %2};" : "=l"(r) : "f"(lo), "f"(hi));
    return r;
}
__device__ __forceinline__ void unpack2(ull v, float& lo, float& hi) {
    asm("mov.b64 {%0, %1}, %2;" : "=f"(lo), "=f"(hi) : "l"(v));
}
__device__ __forceinline__ ull fma2(ull a, ull b, ull c) {
    ull r;
    asm("fma.rn.f32x2 %0, %1, %2, %3;" : "=l"(r) : "l"(a), "l"(b), "l"(c));
    return r;
}
__device__ __forceinline__ ull relu2(ull v) {
    float lo, hi;
    unpack2(v, lo, hi);               // register-half naming: elides
    return pack2(fmaxf(lo, 0.0f), fmaxf(hi, 0.0f));  // 2x FMNMX
}

__global__ __launch_bounds__(256) void moe_kernel(
    const float* __restrict__ x,
    const float* __restrict__ W1, const float* __restrict__ b1,
    const float* __restrict__ W2, const float* __restrict__ b2,
    const float* __restrict__ Wg, const float* __restrict__ bg,
    float* __restrict__ out_mixed, float* __restrict__ out_gate,
    int ngroups)
{
    // Hidden-pair packed weights: each ull = two DISTINCT adjacent hidden
    // units' weights, so LDS.128 feeds FFMA2 with no register packing.
    __shared__ ulonglong2 s_w1a[NEXP * NP];  // { {W1[e,0,2i],W1[e,0,2i+1]}, {W1[e,1,2i],W1[e,1,2i+1]} }
    __shared__ ulonglong2 s_w1b[NEXP * NP];  // { {W1[e,2,2i],W1[e,2,2i+1]}, {b1[e,2i],b1[e,2i+1]} }
    __shared__ ulonglong2 s_w2a[NEXP * NP];  // { {W2[e,2i,0],W2[e,2i+1,0]}, {W2[e,2i,1],W2[e,2i+1,1]} }
    __shared__ ull        s_w2c[NEXP * NP];  // {W2[e,2i,2],W2[e,2i+1,2]}
    __shared__ float4     s_gw[NEXP];        // {Wg[0,e], Wg[1,e], Wg[2,e], bg[e]}
    __shared__ float4     s_b2[NEXP];        // {b2[e,0..2], 0}

    int t = threadIdx.x;
    if (t < NEXP * NP) {
        int e = t / NP, i = t % NP, h = 2 * i;
        const float* w1e = W1 + e * 3 * HID;
        s_w1a[t] = make_ulonglong2(pack2(w1e[0 * HID + h], w1e[0 * HID + h + 1]),
                                   pack2(w1e[1 * HID + h], w1e[1 * HID + h + 1]));
        s_w1b[t] = make_ulonglong2(pack2(w1e[2 * HID + h], w1e[2 * HID + h + 1]),
                                   pack2(b1[e * HID + h], b1[e * HID + h + 1]));
        const float* w2e = W2 + e * HID * 3;
        s_w2a[t] = make_ulonglong2(pack2(w2e[h * 3 + 0], w2e[(h + 1) * 3 + 0]),
                                   pack2(w2e[h * 3 + 1], w2e[(h + 1) * 3 + 1]));
        s_w2c[t] = pack2(w2e[h * 3 + 2], w2e[(h + 1) * 3 + 2]);
    } else if (t < NEXP * NP + NEXP) {
        int e = t - NEXP * NP;
        s_gw[e] = make_float4(Wg[0 * NEXP + e], Wg[1 * NEXP + e], Wg[2 * NEXP + e], bg[e]);
        s_b2[e] = make_float4(b2[e * 3 + 0], b2[e * 3 + 1], b2[e * 3 + 2], 0.0f);
    }
    __syncthreads();

    int gid = blockIdx.x * blockDim.x + threadIdx.x;  // group of 4 tokens
    if (gid >= ngroups) return;

    // ---- Load 4 tokens' x (12 floats = 3x LDG.128) ----
    const float4* x4 = (const float4*)x;
    float4 xa = x4[3 * gid + 0];
    float4 xb = x4[3 * gid + 1];
    float4 xc = x4[3 * gid + 2];
    float x0s[4] = {xa.x, xa.w, xb.z, xc.y};
    float x1s[4] = {xa.y, xb.x, xb.w, xc.z};
    float x2s[4] = {xa.z, xb.y, xc.x, xc.w};

    // Broadcast-packed x: 12 packs per thread total (amortized over 50 iters).
    ull xd0[TPT], xd1[TPT], xd2[TPT];
    #pragma unroll
    for (int k = 0; k < TPT; k++) {
        xd0[k] = pack2(x0s[k], x0s[k]);
        xd1[k] = pack2(x1s[k], x1s[k]);
        xd2[k] = pack2(x2s[k], x2s[k]);
    }

    // ---- Gate: logits + stable softmax (scalar) ----
    float g[TPT][NEXP];
    #pragma unroll
    for (int e = 0; e < NEXP; e++) {
        float4 w = s_gw[e];
        #pragma unroll
        for (int k = 0; k < TPT; k++)
            g[k][e] = fmaf(x0s[k], w.x, fmaf(x1s[k], w.y, fmaf(x2s[k], w.z, w.w)));
    }
    #pragma unroll
    for (int k = 0; k < TPT; k++) {
        float m = g[k][0];
        #pragma unroll
        for (int e = 1; e < NEXP; e++) m = fmaxf(m, g[k][e]);
        float s = 0.0f;
        #pragma unroll
        for (int e = 0; e < NEXP; e++) { g[k][e] = __expf(g[k][e] - m); s += g[k][e]; }
        float inv = __fdividef(1.0f, s);
        #pragma unroll
        for (int e = 0; e < NEXP; e++) g[k][e] *= inv;
    }

    // Store gate output early.
    float4* og = (float4*)out_gate;
    og[5 * gid + 0] = make_float4(g[0][0], g[0][1], g[0][2], g[0][3]);
    og[5 * gid + 1] = make_float4(g[0][4], g[1][0], g[1][1], g[1][2]);
    og[5 * gid + 2] = make_float4(g[1][3], g[1][4], g[2][0], g[2][1]);
    og[5 * gid + 3] = make_float4(g[2][2], g[2][3], g[2][4], g[3][0]);
    og[5 * gid + 4] = make_float4(g[3][1], g[3][2], g[3][3], g[3][4]);

    // ---- Experts: packed-over-hidden fc1 + ReLU + fc2 ----
    float mix0[TPT] = {0.f, 0.f, 0.f, 0.f};
    float mix1[TPT] = {0.f, 0.f, 0.f, 0.f};
    float mix2[TPT] = {0.f, 0.f, 0.f, 0.f};

    for (int e = 0; e < NEXP; e++) {
        // acc init: bias folded in as {b2_o, 0}
        float4 bb = s_b2[e];
        ull bb0 = pack2(bb.x, 0.0f), bb1 = pack2(bb.y, 0.0f), bb2 = pack2(bb.z, 0.0f);
        ull acc0[TPT], acc1[TPT], acc2[TPT];
        #pragma unroll
        for (int k = 0; k < TPT; k++) { acc0[k] = bb0; acc1[k] = bb1; acc2[k] = bb2; }

        #pragma unroll
        for (int i = 0; i < NP; i++) {
            int idx = e * NP + i;
            ulonglong2 w1a = s_w1a[idx];   // {w1x2, w1y2}
            ulonglong2 w1b = s_w1b[idx];   // {w1z2, b1_2}
            ulonglong2 w2a = s_w2a[idx];   // {w2o0_2, w2o1_2}
            ull        w2c = s_w2c[idx];   // w2o2_2
            #pragma unroll
            for (int k = 0; k < TPT; k++) {
                ull hv = fma2(xd0[k], w1a.x, fma2(xd1[k], w1a.y, fma2(xd2[k], w1b.x, w1b.y)));
                hv = relu2(hv);
                acc0[k] = fma2(hv, w2a.x, acc0[k]);
                acc1[k] = fma2(hv, w2a.y, acc1[k]);
                acc2[k] = fma2(hv, w2c,  acc2[k]);
            }
        }
        // Reduce packed lanes and mix by gate.
        #pragma unroll
        for (int k = 0; k < TPT; k++) {
            float lo, hi, ge = g[k][e];
            unpack2(acc0[k], lo, hi); mix0[k] = fmaf(ge, lo + hi, mix0[k]);
            unpack2(acc1[k], lo, hi); mix1[k] = fmaf(ge, lo + hi, mix1[k]);
            unpack2(acc2[k], lo, hi); mix2[k] = fmaf(ge, lo + hi, mix2[k]);
        }
    }

    // ---- Store mixed (12 floats = 3x STG.128) ----
    float4* om = (float4*)out_mixed;
    om[3 * gid + 0] = make_float4(mix0[0], mix1[0], mix2[0], mix0[1]);
    om[3 * gid + 1] = make_float4(mix1[1], mix2[1], mix0[2], mix1[2]);
    om[3 * gid + 2] = make_float4(mix2[2], mix0[3], mix1[3], mix2[3]);
}

extern "C" void kernel_launch(void* const* d_in, const int* in_sizes, int n_in,
                              void* d_out, int out_size)
{
    // Input order per setup_inputs: x, W1, b1, W2, b2, Wg, bg
    const float* x  = (const float*)d_in[0];
    const float* W1 = (const float*)d_in[1];
    const float* b1 = (const float*)d_in[2];
    const float* W2 = (const float*)d_in[3];
    const float* b2 = (const float*)d_in[4];
    const float* Wg = (const float*)d_in[5];
    const float* bg = (const float*)d_in[6];

    int B = in_sizes[0] / 3;           // x is [B, 3]
    int ngroups = B / TPT;             // 4 tokens per thread

    float* out_mixed = (float*)d_out;            // [B, 3]
    float* out_gate  = (float*)d_out + 3 * B;    // [B, 5]

    int threads = 256;
    int blocks = (ngroups + threads - 1) / threads;
    moe_kernel<<<blocks, threads>>>(x, W1, b1, W2, b2, Wg, bg,
                                    out_mixed, out_gate, ngroups);
}